// round 14
// baseline (speedup 1.0000x reference)
#include <cuda_runtime.h>

#define BS 8
#define NA 8400
#define NM 128
#define NC 80
#define TOPK 13
#define EPSF 1e-9f

#define G 8                 // gts per collect block
#define MAXPOS 640          // per-gt candidate cap
#define CB (BS * NM / G)    // 128 collect blocks
#define NGT (BS * NM)       // 1024 gts
#define AB ((BS * NA + 255) / 256)  // 263 argmax blocks (256 anchors each)

typedef unsigned long long ull;

// Scratch (no allocations allowed)
__device__ int   g_count[BS * NA];
__device__ int   g_am[BS * NA];
__device__ float g_cls[BS * NA];
__device__ int   g_nc[NGT];                 // zero-initialized; K2 resets after use
__device__ ull   g_cand[(size_t)NGT * MAXPOS];

// ---------------------------------------------------------------------------
// K1: heterogeneous blocks.
//  blocks [0, CB): pair scan — collect (iou, anchor) candidates per gt into
//    global buffers (cls-independent, so this runs CONCURRENTLY with argmax).
//  blocks [CB, CB+AB): class argmax (4 lanes/anchor, float4 loads) + scratch
//    init for g_count/g_am.
// ---------------------------------------------------------------------------
__global__ __launch_bounds__(1024) void kern_main(const float* __restrict__ pd_scores,
                                                  const float* __restrict__ pd_boxes,
                                                  const float* __restrict__ gt_boxes,
                                                  const float* __restrict__ mask_gt) {
    int tid = threadIdx.x;

    if (blockIdx.x < CB) {
        // ---- collect part ----
        __shared__ float4 sg[G];
        __shared__ float  smk[G];
        int b = blockIdx.x / (NM / G);
        int mbase = (blockIdx.x % (NM / G)) * G;
        if (tid < G) {
            sg[tid] = ((const float4*)gt_boxes)[b * NM + mbase + tid];
            smk[tid] = mask_gt[b * NM + mbase + tid];
        }
        __syncthreads();

        float4 gr[G]; float ga[G]; bool act[G]; int gti[G];
#pragma unroll
        for (int w = 0; w < G; ++w) {
            gr[w] = sg[w];
            ga[w] = (gr[w].z - gr[w].x) * (gr[w].w - gr[w].y);
            act[w] = (smk[w] != 0.0f);
            gti[w] = b * NM + mbase + w;
        }

        const float4* pb = (const float4*)pd_boxes + (size_t)b * NA;

        for (int a = tid; a < NA; a += 1024) {
            float4 p = __ldg(&pb[a]);
            float area_p = (p.z - p.x) * (p.w - p.y);
            float cx = (p.x + p.z) * 0.5f, cy = (p.y + p.w) * 0.5f;
#pragma unroll
            for (int w = 0; w < G; ++w) {
                if (!act[w]) continue;
                float4 g = gr[w];
                float dmin = fminf(fminf(cx - g.x, cy - g.y),
                                   fminf(g.z - cx, g.w - cy));
                if (dmin > EPSF) {
                    float lx = fmaxf(g.x, p.x), ly = fmaxf(g.y, p.y);
                    float rx = fminf(g.z, p.z), ry = fminf(g.w, p.w);
                    float iw = fmaxf(rx - lx, 0.0f), ih = fmaxf(ry - ly, 0.0f);
                    float inter = iw * ih;
                    float iou = inter / (ga[w] + area_p - inter + EPSF);
                    if (iou > 0.0f) {
                        int pos = atomicAdd(&g_nc[gti[w]], 1);
                        if (pos < MAXPOS) {
                            g_cand[(size_t)gti[w] * MAXPOS + pos] =
                                ((ull)__float_as_uint(iou) << 32) |
                                (unsigned)(~(unsigned)a);
                        }
                    }
                }
            }
        }
    } else {
        // ---- argmax part ----
        int abase = (blockIdx.x - CB) * 256;
        if (tid < 256) {
            int a2 = abase + tid;
            if (a2 < BS * NA) { g_count[a2] = 0; g_am[a2] = 0x7FFFFFFF; }
        }

        int wid = tid >> 5;
        int lane = tid & 31;
        int grp = lane >> 2;
        int j = lane & 3;
        int anchor = abase + wid * 8 + grp;   // uniform validity per warp
        if (anchor < BS * NA) {
            const float4* r4 = (const float4*)(pd_scores + (size_t)anchor * NC);

            float4 v[5];
#pragma unroll
            for (int k = 0; k < 5; ++k) v[k] = __ldg(&r4[j + 4 * k]);

            float bv = v[0].x;
            int bi = 4 * j;
#pragma unroll
            for (int k = 0; k < 5; ++k) {
                int cbase = 16 * k + 4 * j;
                if (v[k].x > bv) { bv = v[k].x; bi = cbase + 0; }
                if (v[k].y > bv) { bv = v[k].y; bi = cbase + 1; }
                if (v[k].z > bv) { bv = v[k].z; bi = cbase + 2; }
                if (v[k].w > bv) { bv = v[k].w; bi = cbase + 3; }
            }

            float gm = bv;
            gm = fmaxf(gm, __shfl_xor_sync(0xFFFFFFFFu, gm, 1));
            gm = fmaxf(gm, __shfl_xor_sync(0xFFFFFFFFu, gm, 2));

            int cand = (bv == gm) ? bi : 0x7FFFFFFF;
            cand = min(cand, __shfl_xor_sync(0xFFFFFFFFu, cand, 1));
            cand = min(cand, __shfl_xor_sync(0xFFFFFFFFu, cand, 2));

            if (j == 0) g_cls[anchor] = (float)cand;
        }
    }
}

// ---------------------------------------------------------------------------
// K2: one warp per gt. Forms align keys from candidates (al = cls * iou^6,
// bit-identical arithmetic), extracts top-13 (value desc, index asc),
// fills with lowest-index zero-align anchors when npos < 13.
// Resets g_nc for the next launch.
// ---------------------------------------------------------------------------
__global__ __launch_bounds__(128) void kern_select(const float* __restrict__ mask_gt) {
    __shared__ ull K[4][MAXPOS];
    __shared__ unsigned selbuf[4][TOPK];

    int tid = threadIdx.x, wid = tid >> 5, lane = tid & 31;
    int gt = blockIdx.x * 4 + wid;
    int b = gt / NM;
    int m = gt - b * NM;
    int cbase = b * NA;

    float mk = mask_gt[gt];
    if (mk == 0.0f) {
        // align all zero: top-13 = anchors 0..12
        if (lane < TOPK) {
            atomicAdd(&g_count[cbase + lane], 1);
            atomicMin(&g_am[cbase + lane], m);
        }
        if (lane == 0) g_nc[gt] = 0;
        return;
    }

    int n = min(g_nc[gt], MAXPOS);
    if (lane == 0) g_nc[gt] = 0;
    const ull* src = g_cand + (size_t)gt * MAXPOS;

    int npos = 0;
    for (int i = lane; i < n; i += 32) {
        ull cnd = src[i];
        unsigned a = ~(unsigned)(cnd & 0xFFFFFFFFull);
        float iou = __uint_as_float((unsigned)(cnd >> 32));
        float c = g_cls[cbase + a];
        float i2 = iou * iou;
        float al = c * ((i2 * i2) * i2);
        ull key = 0;
        if (al > 0.0f) {
            key = ((ull)__float_as_uint(al) << 32) | (unsigned)(~a);
            ++npos;
        }
        K[wid][i] = key;
    }
#pragma unroll
    for (int off = 16; off > 0; off >>= 1)
        npos += __shfl_xor_sync(0xFFFFFFFFu, npos, off);
    __syncwarp();

    int sel = min(npos, TOPK);
    for (int r = 0; r < sel; ++r) {
        ull bk = 0; int bp = -1;
        for (int i = lane; i < n; i += 32) {
            ull k = K[wid][i];
            if (k > bk) { bk = k; bp = i; }
        }
#pragma unroll
        for (int off = 16; off > 0; off >>= 1) {
            ull ok = __shfl_xor_sync(0xFFFFFFFFu, bk, off);
            int op = __shfl_xor_sync(0xFFFFFFFFu, bp, off);
            if (ok > bk) { bk = ok; bp = op; }
        }
        if (lane == 0) {
            unsigned aa = ~(unsigned)(bk & 0xFFFFFFFFull);
            selbuf[wid][r] = aa;
            atomicAdd(&g_count[cbase + aa], 1);
            atomicMin(&g_am[cbase + aa], m);
            K[wid][bp] = 0;
        }
        __syncwarp();
    }
    __syncwarp();
    if (lane == 0 && npos < TOPK) {
        int f = TOPK - npos;
        for (int a = 0; f > 0; ++a) {
            bool found = false;
            for (int i = 0; i < npos; ++i)
                if (selbuf[wid][i] == (unsigned)a) { found = true; break; }
            if (!found) {
                atomicAdd(&g_count[cbase + a], 1);
                atomicMin(&g_am[cbase + a], m);
                --f;
            }
        }
    }
}

// ---------------------------------------------------------------------------
// K3: classify -> block-worklist multi resolution -> fully coalesced output
// emission, including the one-hot ts region.
// ---------------------------------------------------------------------------
__global__ __launch_bounds__(256) void kern_out(const float* __restrict__ pd_boxes,
                                                const int* __restrict__ gt_labels,
                                                const float* __restrict__ gt_boxes,
                                                float* __restrict__ out) {
    __shared__ int s_wn;
    __shared__ int s_wl[256];
    __shared__ int s_res[256];
    __shared__ int s_lbl[256];

    int base = blockIdx.x * 256;
    int tid = threadIdx.x;
    int idx = base + tid;
    bool valid = idx < BS * NA;
    if (tid == 0) s_wn = 0;
    __syncthreads();

    int c = valid ? g_count[idx] : 0;
    int res = 0;
    if (c == 1) res = g_am[idx] | 0x10000;
    else if (c > 1) {
        int pos = atomicAdd(&s_wn, 1);
        s_wl[pos] = tid;
    }
    s_res[tid] = res;
    __syncthreads();

    int wid = tid >> 5, lane = tid & 31;
    int nw = s_wn;
    for (int e = wid; e < nw; e += 8) {
        int t2 = s_wl[e];
        int idx2 = base + t2;
        int b2 = idx2 / NA;
        float4 p = ((const float4*)pd_boxes)[idx2];
        float area_p = (p.z - p.x) * (p.w - p.y);
        const float4* gb = (const float4*)gt_boxes + (size_t)b2 * NM;

        ull best = 0;
        for (int i = 0; i < NM / 32; ++i) {
            int m = lane + i * 32;
            float4 g = gb[m];
            float lx = fmaxf(g.x, p.x), ly = fmaxf(g.y, p.y);
            float rx = fminf(g.z, p.z), ry = fminf(g.w, p.w);
            float iw = fmaxf(rx - lx, 0.0f), ih = fmaxf(ry - ly, 0.0f);
            float inter = iw * ih;
            float area_g = (g.z - g.x) * (g.w - g.y);
            float iou = inter / (area_g + area_p - inter + EPSF);
            ull key = ((ull)__float_as_uint(iou) << 32) | (unsigned)(~(unsigned)m);
            if (key > best) best = key;
        }
        for (int off = 16; off > 0; off >>= 1) {
            ull o = __shfl_xor_sync(0xFFFFFFFFu, best, off);
            if (o > best) best = o;
        }
        if (lane == 0)
            s_res[t2] = (int)(~(unsigned)(best & 0xFFFFFFFFull)) | 0x10000;
    }
    __syncthreads();

    float* tl = out;
    float* tb = out + (size_t)BS * NA;
    float* mo = out + (size_t)BS * NA * 85;

    int lbl = NC;
    if (valid) {
        int b = idx / NA;
        int r = s_res[tid];
        int am = r & 0xFFFF;
        float msk = (r & 0x10000) ? 1.0f : 0.0f;
        if (msk > 0.0f) lbl = gt_labels[b * NM + am];
        tl[idx] = (float)lbl;
        ((float4*)tb)[idx] = ((const float4*)gt_boxes)[b * NM + am];
        mo[idx] = msk;
    }
    s_lbl[tid] = lbl;
    __syncthreads();

    int nloc = min(256, BS * NA - base);
    float4* tsp = (float4*)(out + (size_t)BS * NA * 5) + (size_t)base * (NC / 4);
    for (int i = tid; i < nloc * (NC / 4); i += 256) {
        int al = i / (NC / 4);
        int q  = i - al * (NC / 4);
        int l2 = s_lbl[al];
        float4 v = make_float4(0.f, 0.f, 0.f, 0.f);
        if ((l2 >> 2) == q) ((float*)&v)[l2 & 3] = 1.0f;
        tsp[i] = v;
    }
}

// ---------------------------------------------------------------------------
extern "C" void kernel_launch(void* const* d_in, const int* in_sizes, int n_in,
                              void* d_out, int out_size) {
    const float* pd_scores = (const float*)d_in[0];
    const float* pd_boxes  = (const float*)d_in[1];
    const int*   gt_labels = (const int*)d_in[2];
    const float* gt_boxes  = (const float*)d_in[3];
    const float* mask_gt   = (const float*)d_in[4];
    float* out = (float*)d_out;

    kern_main<<<CB + AB, 1024>>>(pd_scores, pd_boxes, gt_boxes, mask_gt);
    kern_select<<<NGT / 4, 128>>>(mask_gt);
    kern_out<<<AB, 256>>>(pd_boxes, gt_labels, gt_boxes, out);
}

// round 15
// speedup vs baseline: 1.3444x; 1.3444x over previous
#include <cuda_runtime.h>

#define BS 8
#define NA 8400
#define NM 128
#define NC 80
#define TOPK 13
#define EPSF 1e-9f

#define G 8          // gts per topk block
#define MAXPOS 640   // per-gt positive-candidate buffer cap
#define TKT 1024     // topk threads per block

typedef unsigned long long ull;

// Scratch (no allocations allowed)
__device__ int   g_count[BS * NA];
__device__ int   g_am[BS * NA];
__device__ float g_cls[BS * NA];

// ---------------------------------------------------------------------------
// K2: one block per (b, group of G gts), 1024 threads. Phase 1 collects
// anchors with align > 0 into per-gt shared buffers (2x unrolled anchor scan
// for MLP). Phase 2: one warp per gt extracts top-13 and updates count/am.
// ---------------------------------------------------------------------------
__global__ __launch_bounds__(TKT) void kern_topk(const float* __restrict__ pd_boxes,
                                                 const float* __restrict__ gt_boxes,
                                                 const float* __restrict__ mask_gt) {
    __shared__ int  sn[G];
    __shared__ ull  keys[G][MAXPOS];
    __shared__ unsigned selbuf[G][TOPK];
    __shared__ float4 sg[G];
    __shared__ float  smk[G];

    int b = blockIdx.x / (NM / G);
    int mbase = (blockIdx.x % (NM / G)) * G;
    int tid = threadIdx.x;

    if (tid < G) {
        sn[tid] = 0;
        sg[tid] = ((const float4*)gt_boxes)[b * NM + mbase + tid];
        smk[tid] = mask_gt[b * NM + mbase + tid];
    }
    __syncthreads();

    float4 gr[G]; float ga[G]; bool act[G];
#pragma unroll
    for (int w = 0; w < G; ++w) {
        gr[w] = sg[w];
        ga[w] = (gr[w].z - gr[w].x) * (gr[w].w - gr[w].y);
        act[w] = (smk[w] != 0.0f);
    }

    const float4* pb = (const float4*)pd_boxes + (size_t)b * NA;
    const float*  cl = g_cls + (size_t)b * NA;

    for (int a = tid; a < NA; a += 2 * TKT) {
        int a2 = a + TKT;
        bool has2 = a2 < NA;
        // issue both anchors' loads before any processing (MLP=2)
        float4 p1 = __ldg(&pb[a]);
        float  c1 = __ldg(&cl[a]);
        float4 p2; float c2 = 0.0f;
        if (has2) { p2 = __ldg(&pb[a2]); c2 = __ldg(&cl[a2]); }

        {
            float area_p = (p1.z - p1.x) * (p1.w - p1.y);
            float cx = (p1.x + p1.z) * 0.5f, cy = (p1.y + p1.w) * 0.5f;
#pragma unroll
            for (int w = 0; w < G; ++w) {
                if (!act[w]) continue;
                float4 g = gr[w];
                float dmin = fminf(fminf(cx - g.x, cy - g.y),
                                   fminf(g.z - cx, g.w - cy));
                if (dmin > EPSF && c1 > 0.0f) {
                    float lx = fmaxf(g.x, p1.x), ly = fmaxf(g.y, p1.y);
                    float rx = fminf(g.z, p1.z), ry = fminf(g.w, p1.w);
                    float iw = fmaxf(rx - lx, 0.0f), ih = fmaxf(ry - ly, 0.0f);
                    float inter = iw * ih;
                    float iou = inter / (ga[w] + area_p - inter + EPSF);
                    float i2 = iou * iou;
                    float al = c1 * ((i2 * i2) * i2);
                    if (al > 0.0f) {
                        int pos = atomicAdd(&sn[w], 1);
                        if (pos < MAXPOS) {
                            keys[w][pos] = ((ull)__float_as_uint(al) << 32) |
                                           (unsigned)(~(unsigned)a);
                        }
                    }
                }
            }
        }
        if (has2) {
            float area_p = (p2.z - p2.x) * (p2.w - p2.y);
            float cx = (p2.x + p2.z) * 0.5f, cy = (p2.y + p2.w) * 0.5f;
#pragma unroll
            for (int w = 0; w < G; ++w) {
                if (!act[w]) continue;
                float4 g = gr[w];
                float dmin = fminf(fminf(cx - g.x, cy - g.y),
                                   fminf(g.z - cx, g.w - cy));
                if (dmin > EPSF && c2 > 0.0f) {
                    float lx = fmaxf(g.x, p2.x), ly = fmaxf(g.y, p2.y);
                    float rx = fminf(g.z, p2.z), ry = fminf(g.w, p2.w);
                    float iw = fmaxf(rx - lx, 0.0f), ih = fmaxf(ry - ly, 0.0f);
                    float inter = iw * ih;
                    float iou = inter / (ga[w] + area_p - inter + EPSF);
                    float i2 = iou * iou;
                    float al = c2 * ((i2 * i2) * i2);
                    if (al > 0.0f) {
                        int pos = atomicAdd(&sn[w], 1);
                        if (pos < MAXPOS) {
                            keys[w][pos] = ((ull)__float_as_uint(al) << 32) |
                                           (unsigned)(~(unsigned)a2);
                        }
                    }
                }
            }
        }
    }
    __syncthreads();

    int wid = tid >> 5, lane = tid & 31;
    if (wid < G) {
        int m = mbase + wid;
        if (!act[wid]) {
            if (lane < TOPK) {
                atomicAdd(&g_count[b * NA + lane], 1);
                atomicMin(&g_am[b * NA + lane], m);
            }
        } else {
            int n = min(sn[wid], MAXPOS);
            ull* K = keys[wid];
            int sel = min(n, TOPK);
            for (int r = 0; r < sel; ++r) {
                ull bk = 0; int bp = -1;
                for (int i = lane; i < n; i += 32) {
                    ull k = K[i];
                    if (k > bk) { bk = k; bp = i; }
                }
#pragma unroll
                for (int off = 16; off > 0; off >>= 1) {
                    ull ok = __shfl_xor_sync(0xFFFFFFFFu, bk, off);
                    int op = __shfl_xor_sync(0xFFFFFFFFu, bp, off);
                    if (ok > bk) { bk = ok; bp = op; }
                }
                if (lane == 0) {
                    unsigned aa = ~(unsigned)(bk & 0xFFFFFFFFull);
                    selbuf[wid][r] = aa;
                    atomicAdd(&g_count[b * NA + aa], 1);
                    atomicMin(&g_am[b * NA + aa], m);
                    K[bp] = 0;
                }
                __syncwarp();
            }
            __syncwarp();
            if (lane == 0 && n < TOPK) {
                int f = TOPK - n;
                for (int a = 0; f > 0; ++a) {
                    bool pos = false;
                    for (int i = 0; i < n; ++i)
                        if (selbuf[wid][i] == (unsigned)a) { pos = true; break; }
                    if (!pos) {
                        atomicAdd(&g_count[b * NA + a], 1);
                        atomicMin(&g_am[b * NA + a], m);
                        --f;
                    }
                }
            }
        }
    }
}

// ---------------------------------------------------------------------------
// K1: class argmax with 4 lanes per anchor, float4 loads (5 per lane, MLP=5),
// 4 shuffle rounds per anchor. 64 anchors/block, 1050 blocks (best measured).
// ---------------------------------------------------------------------------
__global__ __launch_bounds__(256) void kern_argmax(const float* __restrict__ pd_scores) {
    int abase = blockIdx.x * 64;
    if (threadIdx.x < 64) {
        g_count[abase + threadIdx.x] = 0;
        g_am[abase + threadIdx.x] = 0x7FFFFFFF;
    }

    int wid = threadIdx.x >> 5;
    int lane = threadIdx.x & 31;
    int grp = lane >> 2;
    int j = lane & 3;
    int anchor = abase + wid * 8 + grp;

    const float4* r4 = (const float4*)(pd_scores + (size_t)anchor * NC);

    float4 v[5];
#pragma unroll
    for (int k = 0; k < 5; ++k) v[k] = __ldg(&r4[j + 4 * k]);

    float bv = v[0].x;
    int bi = 4 * j;
#pragma unroll
    for (int k = 0; k < 5; ++k) {
        int cbase = 16 * k + 4 * j;
        if (v[k].x > bv) { bv = v[k].x; bi = cbase + 0; }
        if (v[k].y > bv) { bv = v[k].y; bi = cbase + 1; }
        if (v[k].z > bv) { bv = v[k].z; bi = cbase + 2; }
        if (v[k].w > bv) { bv = v[k].w; bi = cbase + 3; }
    }

    float gm = bv;
    gm = fmaxf(gm, __shfl_xor_sync(0xFFFFFFFFu, gm, 1));
    gm = fmaxf(gm, __shfl_xor_sync(0xFFFFFFFFu, gm, 2));

    int cand = (bv == gm) ? bi : 0x7FFFFFFF;
    cand = min(cand, __shfl_xor_sync(0xFFFFFFFFu, cand, 1));
    cand = min(cand, __shfl_xor_sync(0xFFFFFFFFu, cand, 2));

    if (j == 0) g_cls[anchor] = (float)cand;
}

// ---------------------------------------------------------------------------
// K3: classify -> block-worklist multi resolution -> fully coalesced output
// emission, including the one-hot ts region.
// s_res[t] = gt index in low 16 bits, bit 16 set => assigned (mask=1).
// ---------------------------------------------------------------------------
__global__ __launch_bounds__(256) void kern_out(const float* __restrict__ pd_boxes,
                                                const int* __restrict__ gt_labels,
                                                const float* __restrict__ gt_boxes,
                                                float* __restrict__ out) {
    __shared__ int s_wn;
    __shared__ int s_wl[256];
    __shared__ int s_res[256];
    __shared__ int s_lbl[256];

    int base = blockIdx.x * 256;
    int tid = threadIdx.x;
    int idx = base + tid;
    bool valid = idx < BS * NA;
    if (tid == 0) s_wn = 0;
    __syncthreads();

    int c = valid ? g_count[idx] : 0;
    int res = 0;
    if (c == 1) res = g_am[idx] | 0x10000;
    else if (c > 1) {
        int pos = atomicAdd(&s_wn, 1);
        s_wl[pos] = tid;
    }
    s_res[tid] = res;
    __syncthreads();

    int wid = tid >> 5, lane = tid & 31;
    int nw = s_wn;
    for (int e = wid; e < nw; e += 8) {
        int t2 = s_wl[e];
        int idx2 = base + t2;
        int b2 = idx2 / NA;
        float4 p = ((const float4*)pd_boxes)[idx2];
        float area_p = (p.z - p.x) * (p.w - p.y);
        const float4* gb = (const float4*)gt_boxes + (size_t)b2 * NM;

        ull best = 0;
        for (int i = 0; i < NM / 32; ++i) {
            int m = lane + i * 32;
            float4 g = gb[m];
            float lx = fmaxf(g.x, p.x), ly = fmaxf(g.y, p.y);
            float rx = fminf(g.z, p.z), ry = fminf(g.w, p.w);
            float iw = fmaxf(rx - lx, 0.0f), ih = fmaxf(ry - ly, 0.0f);
            float inter = iw * ih;
            float area_g = (g.z - g.x) * (g.w - g.y);
            float iou = inter / (area_g + area_p - inter + EPSF);
            ull key = ((ull)__float_as_uint(iou) << 32) | (unsigned)(~(unsigned)m);
            if (key > best) best = key;
        }
        for (int off = 16; off > 0; off >>= 1) {
            ull o = __shfl_xor_sync(0xFFFFFFFFu, best, off);
            if (o > best) best = o;
        }
        if (lane == 0)
            s_res[t2] = (int)(~(unsigned)(best & 0xFFFFFFFFull)) | 0x10000;
    }
    __syncthreads();

    float* tl = out;
    float* tb = out + (size_t)BS * NA;
    float* mo = out + (size_t)BS * NA * 85;

    int lbl = NC;
    if (valid) {
        int b = idx / NA;
        int r = s_res[tid];
        int am = r & 0xFFFF;
        float msk = (r & 0x10000) ? 1.0f : 0.0f;
        if (msk > 0.0f) lbl = gt_labels[b * NM + am];
        tl[idx] = (float)lbl;
        ((float4*)tb)[idx] = ((const float4*)gt_boxes)[b * NM + am];
        mo[idx] = msk;
    }
    s_lbl[tid] = lbl;
    __syncthreads();

    int nloc = min(256, BS * NA - base);
    float4* tsp = (float4*)(out + (size_t)BS * NA * 5) + (size_t)base * (NC / 4);
    for (int i = tid; i < nloc * (NC / 4); i += 256) {
        int al = i / (NC / 4);
        int q  = i - al * (NC / 4);
        int l2 = s_lbl[al];
        float4 v = make_float4(0.f, 0.f, 0.f, 0.f);
        if ((l2 >> 2) == q) ((float*)&v)[l2 & 3] = 1.0f;
        tsp[i] = v;
    }
}

// ---------------------------------------------------------------------------
extern "C" void kernel_launch(void* const* d_in, const int* in_sizes, int n_in,
                              void* d_out, int out_size) {
    const float* pd_scores = (const float*)d_in[0];
    const float* pd_boxes  = (const float*)d_in[1];
    const int*   gt_labels = (const int*)d_in[2];
    const float* gt_boxes  = (const float*)d_in[3];
    const float* mask_gt   = (const float*)d_in[4];
    float* out = (float*)d_out;

    int n = BS * NA;
    kern_argmax<<<n / 64, 256>>>(pd_scores);
    kern_topk<<<BS * NM / G, TKT>>>(pd_boxes, gt_boxes, mask_gt);
    kern_out<<<(n + 255) / 256, 256>>>(pd_boxes, gt_labels, gt_boxes, out);
}